// round 14
// baseline (speedup 1.0000x reference)
#include <cuda_runtime.h>
#include <cuda_bf16.h>

#define NN 262144
#define BB 4096
#define NEGV -1000000000.0f

typedef unsigned long long ull;

// ---- packed f32x2 helpers ----
__device__ __forceinline__ ull pk2(float a, float b) {
    ull r;
    asm("mov.b64 %0, {%1, %2};" : "=l"(r) : "f"(a), "f"(b));
    return r;
}
__device__ __forceinline__ void upk2(ull v, float& a, float& b) {
    asm("mov.b64 {%0, %1}, %2;" : "=f"(a), "=f"(b) : "l"(v));
}
__device__ __forceinline__ ull fma2(ull a, ull b, ull c) {
    ull r;
    asm("fma.rn.f32x2 %0, %1, %2, %3;" : "=l"(r) : "l"(a), "l"(b), "l"(c));
    return r;
}

// Single fused kernel: warp = batch.
//  - lower_bound(batch, b) via 32-ary warp search
//  - layer1 mainloop computes node@W1a AND glob@W1b in the same k-loop
//  - packed smem-W2t epilogue
__global__ void __launch_bounds__(128, 7) maneuver_kernel(
    const float* __restrict__ nf, const float* __restrict__ glob,
    const int* __restrict__ gmask, const int* __restrict__ batch,
    const int* __restrict__ mm,
    const float* __restrict__ W1, const float* __restrict__ b1,
    const float* __restrict__ W2, const float* __restrict__ b2,
    float* __restrict__ out)
{
    __shared__ float sxp_all[4 * 1024];
    __shared__ float sglob_all[4 * 128];
    __shared__ float sw2t_all[4 * 462];     // per-warp W2^T, stride 66
    const int tid  = threadIdx.x;
    const int w    = tid >> 5;
    const int lane = tid & 31;
    float* sxp  = sxp_all + w * 1024;       // 128 k x 8 floats
    float* sgl  = sglob_all + w * 128;
    float* sw2t = sw2t_all + w * 462;

    const int b = blockIdx.x * 4 + w;

    // independent early loads (hide DRAM): glob row, b1, masks
    float4 gl4 = ((const float4*)glob)[b * 32 + lane];
    float2 b1v = *(const float2*)&b1[2 * lane];
    int mm0 = mm[b * 56 + lane];
    int mm1 = (lane < 24) ? mm[b * 56 + 32 + lane] : 0;

    // stage W2^T: idx = j*7+d contiguous LDG, store [d][j] stride 66
    #pragma unroll
    for (int t = 0; t < 14; ++t) {
        int idx = t * 32 + lane;
        float v = __ldg(&W2[idx]);
        int j = idx / 7, d = idx - 7 * j;
        sw2t[d * 66 + j] = v;
    }

    // ---- 32-ary lower_bound: s = first i with batch[i] >= b ----
    int lo = 0, hi = NN;
    while (hi - lo > 32) {
        int span = hi - lo;
        int pos = lo + (int)(((long long)span * (lane + 1)) >> 5);
        bool c = false;
        if (lane < 31 && pos < NN) c = (batch[pos] < b);
        unsigned bal = __ballot_sync(0xffffffffu, c);
        int t = __popc(bal);
        int nlo = (t > 0) ? lo + (int)(((long long)span * t) >> 5) + 1 : lo;
        int nhi = (t < 31) ? lo + (int)(((long long)span * (t + 1)) >> 5) : hi;
        lo = nlo; hi = nhi;
    }
    {
        int pos = lo + lane;
        bool c = (pos < hi && pos < NN) ? (batch[pos] < b) : false;
        unsigned bal = __ballot_sync(0xffffffffu, c);
        lo = lo + __popc(bal);
    }
    const int s = lo;

    // stash glob row for the merged gb stream
    ((float4*)sgl)[lane] = gl4;

    // ---- scan for first <=8 selected nodes; batch[i]==b bounds the segment ----
    int cnt = 0;
    int my_node = -1;
    int base = s;
    while (true) {
        int i = base + lane;
        int bt = (i < NN) ? batch[i] : 0x7fffffff;
        bool m = (bt == b) ? (gmask[i] != 0) : false;
        unsigned bal = __ballot_sync(0xffffffffu, m);
        int ns = __popc(bal);
        int want = lane - cnt;
        if (lane < 8 && want >= 0 && want < ns) {
            unsigned mk = bal;
            #pragma unroll
            for (int t = 0; t < 7; ++t) if (t < want) mk &= (mk - 1u);
            my_node = base + (__ffs(mk) - 1);
        }
        cnt += ns;
        bool over = (bt > b);
        if (cnt >= 8 || __ballot_sync(0xffffffffu, over)) break;
        base += 32;
    }
    const int V = cnt < 8 ? cnt : 8;

    // ---- gather 8 node rows as float4 (lane owns cols 4l..4l+3) ----
    const float4* nf4 = (const float4*)nf;
    float4 a[8];
    #pragma unroll
    for (int n = 0; n < 8; ++n) {
        int ni = __shfl_sync(0xffffffffu, my_node, n);
        a[n] = (ni >= 0) ? nf4[(size_t)ni * 32 + lane]
                         : make_float4(0.f, 0.f, 0.f, 0.f);
    }

    // ---- transpose x to smem: k = 4*lane + j, 8 floats per k ----
    #pragma unroll
    for (int j = 0; j < 4; ++j) {
        int k = 4 * lane + j;
        float* p = &sxp[k * 8];
        ((float4*)p)[0] = make_float4(((const float*)&a[0])[j], ((const float*)&a[1])[j],
                                      ((const float*)&a[2])[j], ((const float*)&a[3])[j]);
        ((float4*)p)[1] = make_float4(((const float*)&a[4])[j], ((const float*)&a[5])[j],
                                      ((const float*)&a[6])[j], ((const float*)&a[7])[j]);
    }
    __syncwarp();

    // ---- merged layer-1 mainloop: 8 nodes x 2 hidden per lane + gb stream ----
    const float2* W1v = (const float2*)W1;
    ull acc0[4], acc1[4];
    #pragma unroll
    for (int p = 0; p < 4; ++p) {
        acc0[p] = pk2(0.f, 0.f);
        acc1[p] = pk2(0.f, 0.f);
    }
    ull accg = pk2(b1v.x, b1v.y);   // (hidden 2l, 2l+1) for this batch
    #pragma unroll 4
    for (int k4 = 0; k4 < 32; ++k4) {
        float4 xg4 = *(const float4*)&sgl[k4 * 4];   // LDS.128 broadcast
        #pragma unroll
        for (int j = 0; j < 4; ++j) {
            int k = 4 * k4 + j;
            float2 wv = __ldg(&W1v[k * 32 + lane]);          // W1a row k
            float2 wg = __ldg(&W1v[(128 + k) * 32 + lane]);  // W1b row k
            float xgk = (j == 0) ? xg4.x : (j == 1) ? xg4.y : (j == 2) ? xg4.z : xg4.w;
            ull ww0 = pk2(wv.x, wv.x);
            ull ww1 = pk2(wv.y, wv.y);
            ulonglong2 xA = *(const ulonglong2*)&sxp[k * 8];
            ulonglong2 xB = *(const ulonglong2*)&sxp[k * 8 + 4];
            acc0[0] = fma2(xA.x, ww0, acc0[0]);  acc1[0] = fma2(xA.x, ww1, acc1[0]);
            acc0[1] = fma2(xA.y, ww0, acc0[1]);  acc1[1] = fma2(xA.y, ww1, acc1[1]);
            acc0[2] = fma2(xB.x, ww0, acc0[2]);  acc1[2] = fma2(xB.x, ww1, acc1[2]);
            acc0[3] = fma2(xB.y, ww0, acc0[3]);  acc1[3] = fma2(xB.y, ww1, acc1[3]);
            accg    = fma2(pk2(wg.x, wg.y), pk2(xgk, xgk), accg);
        }
    }
    float g0, g1;
    upk2(accg, g0, g1);

    // ---- relu(acc + gb), stash h (reuse sxp): h[n*66 + j] ----
    __syncwarp();
    #pragma unroll
    for (int p = 0; p < 4; ++p) {
        float hx0, hy0, hx1, hy1;
        upk2(acc0[p], hx0, hy0);   // hidden 2l : node 2p (x), node 2p+1 (y)
        upk2(acc1[p], hx1, hy1);   // hidden 2l+1
        sxp[(2 * p) * 66 + 2 * lane]         = fmaxf(hx0 + g0, 0.f);
        sxp[(2 * p) * 66 + 2 * lane + 1]     = fmaxf(hx1 + g1, 0.f);
        sxp[(2 * p + 1) * 66 + 2 * lane]     = fmaxf(hy0 + g0, 0.f);
        sxp[(2 * p + 1) * 66 + 2 * lane + 1] = fmaxf(hy1 + g1, 0.f);
    }
    __syncwarp();

    // ---- layer 2 (packed) + mask + store: 56 outputs ----
    #pragma unroll
    for (int p = 0; p < 2; ++p) {
        int idx = p * 32 + lane;
        int mv  = p == 0 ? mm0 : mm1;
        if (idx < 56) {
            int n = idx / 7, d = idx - n * 7;
            float val = NEGV;
            if (n < V && mv != 0) {
                const float* hb = &sxp[n * 66];
                const float* wt = &sw2t[d * 66];
                ull acc2 = pk2(0.f, 0.f);
                #pragma unroll
                for (int j2 = 0; j2 < 32; ++j2)
                    acc2 = fma2(*(const ull*)&hb[2 * j2], *(const ull*)&wt[2 * j2], acc2);
                float s0, s1;
                upk2(acc2, s0, s1);
                val = s0 + s1 + __ldg(&b2[d]);
            }
            out[b * 56 + idx] = val;
        }
    }
}

extern "C" void kernel_launch(void* const* d_in, const int* in_sizes, int n_in,
                              void* d_out, int out_size) {
    const float* nf    = (const float*)d_in[0];
    const float* glob  = (const float*)d_in[1];
    const int*   gmask = (const int*)d_in[2];
    const int*   batch = (const int*)d_in[3];
    const int*   mm    = (const int*)d_in[4];
    const float* W1    = (const float*)d_in[5];
    const float* b1    = (const float*)d_in[6];
    const float* W2    = (const float*)d_in[7];
    const float* b2    = (const float*)d_in[8];
    float*       out   = (float*)d_out;

    maneuver_kernel<<<BB / 4, 128>>>(nf, glob, gmask, batch, mm, W1, b1, W2, b2, out);
}

// round 16
// speedup vs baseline: 1.0714x; 1.0714x over previous
#include <cuda_runtime.h>
#include <cuda_bf16.h>

#define NN 262144
#define BB 4096
#define NEGV -1000000000.0f
#define SGT 6     // sglobT row stride (floats)

typedef unsigned long long ull;

// ---- packed f32x2 helpers ----
__device__ __forceinline__ ull pk2(float a, float b) {
    ull r;
    asm("mov.b64 %0, {%1, %2};" : "=l"(r) : "f"(a), "f"(b));
    return r;
}
__device__ __forceinline__ void upk2(ull v, float& a, float& b) {
    asm("mov.b64 {%0, %1}, %2;" : "=f"(a), "=f"(b) : "l"(v));
}
__device__ __forceinline__ ull fma2(ull a, ull b, ull c) {
    ull r;
    asm("fma.rn.f32x2 %0, %1, %2, %3;" : "=l"(r) : "l"(a), "l"(b), "l"(c));
    return r;
}

// Single fused kernel: warp = batch (4 per CTA).
//  - 32-ary warp lower_bound + ballot scan for first <=8 selected nodes
//  - cooperative gb: each warp does k-quarter of glob@W1b for ALL 4 batches
//  - layer1 mainloop: 8 nodes x 2 hidden per lane, W1a via L1 (4 wf/k)
//  - CTA-shared W2^T packed epilogue
__global__ void __launch_bounds__(128, 7) maneuver_kernel(
    const float* __restrict__ nf, const float* __restrict__ glob,
    const int* __restrict__ gmask, const int* __restrict__ batch,
    const int* __restrict__ mm,
    const float* __restrict__ W1, const float* __restrict__ b1,
    const float* __restrict__ W2, const float* __restrict__ b2,
    float* __restrict__ out)
{
    __shared__ float sxp_all[4 * 1024];    // per-warp x (k-major, 8/k); reused as h
    __shared__ float sglobT[128 * SGT];    // glob transposed: [k][bw]
    __shared__ float sgbp[16 * 66];        // gb partials: [w*4+bw][2l..]
    __shared__ float sw2t[462];            // CTA-shared W2^T, stride 66
    const int tid  = threadIdx.x;
    const int w    = tid >> 5;
    const int lane = tid & 31;
    float* sxp = sxp_all + w * 1024;

    const int b = blockIdx.x * 4 + w;

    // independent early loads: glob row, b1, masks
    float4 gl4 = ((const float4*)glob)[b * 32 + lane];
    float2 b1v = *(const float2*)&b1[2 * lane];
    int mm0 = mm[b * 56 + lane];
    int mm1 = (lane < 24) ? mm[b * 56 + 32 + lane] : 0;

    // CTA-cooperative W2^T stage: idx = j*7+d contiguous LDG -> [d][j] stride 66
    for (int idx = tid; idx < 448; idx += 128) {
        float v = __ldg(&W2[idx]);
        int j = idx / 7, d = idx - 7 * j;
        sw2t[d * 66 + j] = v;
    }

    // stage glob transposed: sglobT[k][w], k = 4*lane+j
    #pragma unroll
    for (int j = 0; j < 4; ++j) {
        float v = (j == 0) ? gl4.x : (j == 1) ? gl4.y : (j == 2) ? gl4.z : gl4.w;
        sglobT[(4 * lane + j) * SGT + w] = v;
    }

    // ---- 32-ary lower_bound: s = first i with batch[i] >= b ----
    int lo = 0, hi = NN;
    while (hi - lo > 32) {
        int span = hi - lo;
        int pos = lo + (int)(((long long)span * (lane + 1)) >> 5);
        bool c = false;
        if (lane < 31 && pos < NN) c = (batch[pos] < b);
        unsigned bal = __ballot_sync(0xffffffffu, c);
        int t = __popc(bal);
        int nlo = (t > 0) ? lo + (int)(((long long)span * t) >> 5) + 1 : lo;
        int nhi = (t < 31) ? lo + (int)(((long long)span * (t + 1)) >> 5) : hi;
        lo = nlo; hi = nhi;
    }
    {
        int pos = lo + lane;
        bool c = (pos < hi && pos < NN) ? (batch[pos] < b) : false;
        unsigned bal = __ballot_sync(0xffffffffu, c);
        lo = lo + __popc(bal);
    }
    const int s = lo;

    // ---- scan for first <=8 selected nodes; batch[i]==b bounds the segment ----
    int cnt = 0;
    int my_node = -1;
    int base = s;
    while (true) {
        int i = base + lane;
        int bt = (i < NN) ? batch[i] : 0x7fffffff;
        bool m = (bt == b) ? (gmask[i] != 0) : false;
        unsigned bal = __ballot_sync(0xffffffffu, m);
        int ns = __popc(bal);
        int want = lane - cnt;
        if (lane < 8 && want >= 0 && want < ns) {
            unsigned mk = bal;
            #pragma unroll
            for (int t = 0; t < 7; ++t) if (t < want) mk &= (mk - 1u);
            my_node = base + (__ffs(mk) - 1);
        }
        cnt += ns;
        bool over = (bt > b);
        if (cnt >= 8 || __ballot_sync(0xffffffffu, over)) break;
        base += 32;
    }
    const int V = cnt < 8 ? cnt : 8;

    // ---- gather 8 node rows as float4 (lane owns cols 4l..4l+3) ----
    const float4* nf4 = (const float4*)nf;
    float4 a[8];
    #pragma unroll
    for (int n = 0; n < 8; ++n) {
        int ni = __shfl_sync(0xffffffffu, my_node, n);
        a[n] = (ni >= 0) ? nf4[(size_t)ni * 32 + lane]
                         : make_float4(0.f, 0.f, 0.f, 0.f);
    }

    // ---- transpose x to smem: k = 4*lane + j, 8 floats per k ----
    #pragma unroll
    for (int j = 0; j < 4; ++j) {
        int k = 4 * lane + j;
        float* p = &sxp[k * 8];
        ((float4*)p)[0] = make_float4(((const float*)&a[0])[j], ((const float*)&a[1])[j],
                                      ((const float*)&a[2])[j], ((const float*)&a[3])[j]);
        ((float4*)p)[1] = make_float4(((const float*)&a[4])[j], ((const float*)&a[5])[j],
                                      ((const float*)&a[6])[j], ((const float*)&a[7])[j]);
    }
    __syncthreads();   // sglobT + sw2t staged; sxp (warp-local) written

    // ---- cooperative gb partials: this warp covers k in [32w, 32w+32) ----
    const float2* W1v = (const float2*)W1;
    {
        const int k0 = 32 * w;
        ull pacc[4];
        #pragma unroll
        for (int bw = 0; bw < 4; ++bw) pacc[bw] = pk2(0.f, 0.f);
        #pragma unroll 4
        for (int kk = 0; kk < 32; ++kk) {
            int k = k0 + kk;
            float2 wg = __ldg(&W1v[(128 + k) * 32 + lane]);   // W1b row k, hidden 2l,2l+1
            ull wgp = pk2(wg.x, wg.y);
            float2 xa = *(const float2*)&sglobT[k * SGT];      // batches 0,1
            float2 xb = *(const float2*)&sglobT[k * SGT + 2];  // batches 2,3
            pacc[0] = fma2(wgp, pk2(xa.x, xa.x), pacc[0]);
            pacc[1] = fma2(wgp, pk2(xa.y, xa.y), pacc[1]);
            pacc[2] = fma2(wgp, pk2(xb.x, xb.x), pacc[2]);
            pacc[3] = fma2(wgp, pk2(xb.y, xb.y), pacc[3]);
        }
        #pragma unroll
        for (int bw = 0; bw < 4; ++bw) {
            float p0, p1;
            upk2(pacc[bw], p0, p1);
            *(float2*)&sgbp[(w * 4 + bw) * 66 + 2 * lane] = make_float2(p0, p1);
        }
    }
    __syncthreads();   // partials visible

    // reduce gb for own batch (bw == w)
    float g0 = b1v.x, g1 = b1v.y;
    #pragma unroll
    for (int wp = 0; wp < 4; ++wp) {
        float2 pv = *(const float2*)&sgbp[(wp * 4 + w) * 66 + 2 * lane];
        g0 += pv.x;
        g1 += pv.y;
    }

    // ---- layer 1 mainloop: 8 nodes x 2 hidden per lane, W1a via L1 ----
    ull acc0[4], acc1[4];
    #pragma unroll
    for (int p = 0; p < 4; ++p) {
        acc0[p] = pk2(0.f, 0.f);
        acc1[p] = pk2(0.f, 0.f);
    }
    #pragma unroll 4
    for (int k = 0; k < 128; ++k) {
        float2 wv = __ldg(&W1v[k * 32 + lane]);
        ull ww0 = pk2(wv.x, wv.x);
        ull ww1 = pk2(wv.y, wv.y);
        ulonglong2 xA = *(const ulonglong2*)&sxp[k * 8];       // pairs 0,1
        ulonglong2 xB = *(const ulonglong2*)&sxp[k * 8 + 4];   // pairs 2,3
        acc0[0] = fma2(xA.x, ww0, acc0[0]);  acc1[0] = fma2(xA.x, ww1, acc1[0]);
        acc0[1] = fma2(xA.y, ww0, acc0[1]);  acc1[1] = fma2(xA.y, ww1, acc1[1]);
        acc0[2] = fma2(xB.x, ww0, acc0[2]);  acc1[2] = fma2(xB.x, ww1, acc1[2]);
        acc0[3] = fma2(xB.y, ww0, acc0[3]);  acc1[3] = fma2(xB.y, ww1, acc1[3]);
    }

    // ---- relu(acc + gb), stash h (reuse sxp): h[n*66 + j] ----
    __syncwarp();
    #pragma unroll
    for (int p = 0; p < 4; ++p) {
        float hx0, hy0, hx1, hy1;
        upk2(acc0[p], hx0, hy0);   // hidden 2l : node 2p (x), node 2p+1 (y)
        upk2(acc1[p], hx1, hy1);   // hidden 2l+1
        sxp[(2 * p) * 66 + 2 * lane]         = fmaxf(hx0 + g0, 0.f);
        sxp[(2 * p) * 66 + 2 * lane + 1]     = fmaxf(hx1 + g1, 0.f);
        sxp[(2 * p + 1) * 66 + 2 * lane]     = fmaxf(hy0 + g0, 0.f);
        sxp[(2 * p + 1) * 66 + 2 * lane + 1] = fmaxf(hy1 + g1, 0.f);
    }
    __syncwarp();

    // ---- layer 2 (packed, CTA-shared W2^T) + mask + store: 56 outputs ----
    #pragma unroll
    for (int p = 0; p < 2; ++p) {
        int idx = p * 32 + lane;
        int mv  = p == 0 ? mm0 : mm1;
        if (idx < 56) {
            int n = idx / 7, d = idx - n * 7;
            float val = NEGV;
            if (n < V && mv != 0) {
                const float* hb = &sxp[n * 66];
                const float* wt = &sw2t[d * 66];
                ull acc2 = pk2(0.f, 0.f);
                #pragma unroll
                for (int j2 = 0; j2 < 32; ++j2)
                    acc2 = fma2(*(const ull*)&hb[2 * j2], *(const ull*)&wt[2 * j2], acc2);
                float s0, s1;
                upk2(acc2, s0, s1);
                val = s0 + s1 + __ldg(&b2[d]);
            }
            out[b * 56 + idx] = val;
        }
    }
}

extern "C" void kernel_launch(void* const* d_in, const int* in_sizes, int n_in,
                              void* d_out, int out_size) {
    const float* nf    = (const float*)d_in[0];
    const float* glob  = (const float*)d_in[1];
    const int*   gmask = (const int*)d_in[2];
    const int*   batch = (const int*)d_in[3];
    const int*   mm    = (const int*)d_in[4];
    const float* W1    = (const float*)d_in[5];
    const float* b1    = (const float*)d_in[6];
    const float* W2    = (const float*)d_in[7];
    const float* b2    = (const float*)d_in[8];
    float*       out   = (float*)d_out;

    maneuver_kernel<<<BB / 4, 128>>>(nf, glob, gmask, batch, mm, W1, b1, W2, b2, out);
}